// round 14
// baseline (speedup 1.0000x reference)
#include <cuda_runtime.h>
#include <cuda_fp16.h>

// Correlation cost volume: out[b, dy*9+dx, y, x] = (1/C) * sum_c in1[b,c,y,x] * in2pad[b,c,y+dy-4,x+dx-4]
// B=8, C=128, H=96, W=128, d=4 -> 81 displacements.
//
// Round 10: R9 (fp16 in2 tile, LDS.64 windows) + in1 tile ALSO fp16-packed.
// smem 47.1 -> 38.9 KB => 5 blocks/SM (was 4). s1 row stride 16 u32 is
// naturally conflict-free for LDS.64 (16 mod 32 == 16 -> complementary banks).

#define B_   8
#define C_   128
#define H_   96
#define W_   128
#define ND   9          // 2*d+1
#define CC   16         // channels per smem chunk
#define TY   8          // tile rows per block
#define TX   32         // tile cols per block
#define S1WU 16         // s1 row stride in u32 (32 halves, no pad needed)
#define S2H  10         // in2 tile rows for 3 consecutive dy (8 + 2 halo)
#define S2WU 48         // s2 row stride in u32 (20 data u32 + pad; 48 mod 32 == 16)
#define NTHR 192        // 3 dy-groups x 64 threads

#define S1_U32 (CC * TY * S1WU)        // 2048 u32 = 8 KB
#define S2_U32 (CC * S2H * S2WU)       // 7680 u32 = 30720 B
#define SMEM_BYTES ((S1_U32 + S2_U32) * 4)   // 38912

__device__ __forceinline__ unsigned packh2(float x, float y) {
    __half2 h = __floats2half2_rn(x, y);
    return *reinterpret_cast<unsigned*>(&h);
}
__device__ __forceinline__ float2 unpackh2(unsigned u) {
    __half2 h = *reinterpret_cast<__half2*>(&u);
    return __half22float2(h);
}

__global__ __launch_bounds__(NTHR) void corr_kernel(
    const float* __restrict__ in1,
    const float* __restrict__ in2,
    float* __restrict__ out)
{
    extern __shared__ unsigned smem[];
    unsigned* __restrict__ s1u = smem;            // [CC][TY][S1WU] packed fp16
    unsigned* __restrict__ s2u = smem + S1_U32;   // [CC][S2H][S2WU] packed fp16

    const int t   = threadIdx.x;
    const int x0  = blockIdx.x * TX;
    const int y0  = blockIdx.y * TY;
    const int b   = blockIdx.z / 3;
    const int dyg = blockIdx.z % 3;     // dy group: dy = 3*dyg + g

    const int tg = t & 63;
    const int r  = tg >> 3;             // 0..7  row within tile
    const int q  = tg & 7;              // 0..7  quad of 4 x-pixels
    const int g  = t >> 6;              // 0..2  dy within group
    const int dy = dyg * 3 + g;

    const int ybase = y0 + dyg * 3 - 4; // s2 row 0 == this global y

    float acc[ND][4];
    #pragma unroll
    for (int dx = 0; dx < ND; ++dx)
        #pragma unroll
        for (int p = 0; p < 4; ++p) acc[dx][p] = 0.f;

    // invariant compute pointers (advance per channel)
    // a: halves [q*4, q*4+3] of s1 row r -> u32 [q*2, q*2+1], one aligned LDS.64
    const uint2* a_ptr = (const uint2*)(s1u + r * S1WU + q * 2);
    // w: halves [q*4, q*4+11] of s2 row (r+g) -> u32 [q*2, q*2+5], 3x LDS.64
    const uint2* w_ptr = (const uint2*)(s2u + (r + g) * S2WU + q * 2);

    for (int c0 = 0; c0 < C_; c0 += CC) {
        // ---- fill s1 (fp16-packed): 1024 groups of 4 floats ----
        for (int i = t; i < CC * TY * 8; i += NTHR) {
            const int c   = i >> 6;      // /64
            const int rem = i & 63;
            const int rr  = rem >> 3;
            const int qq  = rem & 7;
            const float4 v = *(const float4*)&in1[
                (((b * C_ + c0 + c) * H_ + y0 + rr) * W_ + x0) + qq * 4];
            *(uint2*)&s1u[(c * TY + rr) * S1WU + qq * 2] =
                make_uint2(packh2(v.x, v.y), packh2(v.z, v.w));
        }

        // ---- fill s2 (fp16-packed): 160 rows x 10 groups of 4 halves ----
        for (int i = t; i < CC * S2H * 10; i += NTHR) {
            const int row = i / 10;            // c*S2H + r2
            const int j4  = i - row * 10;      // 0..9
            const int c   = row / S2H;
            const int r2  = row - c * S2H;
            const int gy  = ybase + r2;
            const int gx  = x0 + j4 * 4 - 4;   // multiple of 4 -> whole-vector predicate
            float4 v = make_float4(0.f, 0.f, 0.f, 0.f);
            if (gy >= 0 && gy < H_ && gx >= 0 && gx <= W_ - 4) {
                v = *(const float4*)&in2[((b * C_ + c0 + c) * H_ + gy) * W_ + gx];
            }
            *(uint2*)&s2u[row * S2WU + j4 * 2] =
                make_uint2(packh2(v.x, v.y), packh2(v.z, v.w));
        }
        __syncthreads();

        // ---- accumulate this chunk: 16 channels x 9 dx x 4 px FMAs ----
        const uint2* p1 = a_ptr;
        const uint2* p2 = w_ptr;
        #pragma unroll 4
        for (int c = 0; c < CC; ++c) {
            const uint2 ua = p1[0];     // 4 halves of a
            const uint2 u0 = p2[0];     // halves 0..3  of window
            const uint2 u1 = p2[1];     // halves 4..7
            const uint2 u2 = p2[2];     // halves 8..11
            p1 += (TY * S1WU) / 2;      // 64 uint2 per channel
            p2 += (S2H * S2WU) / 2;     // 240 uint2 per channel
            const float2 a0 = unpackh2(ua.x);
            const float2 a1 = unpackh2(ua.y);
            const float2 f0 = unpackh2(u0.x);
            const float2 f1 = unpackh2(u0.y);
            const float2 f2 = unpackh2(u1.x);
            const float2 f3 = unpackh2(u1.y);
            const float2 f4 = unpackh2(u2.x);
            const float2 f5 = unpackh2(u2.y);
            const float a[4]  = { a0.x, a0.y, a1.x, a1.y };
            const float w[12] = { f0.x, f0.y, f1.x, f1.y,
                                  f2.x, f2.y, f3.x, f3.y,
                                  f4.x, f4.y, f5.x, f5.y };
            #pragma unroll
            for (int dx = 0; dx < ND; ++dx) {
                acc[dx][0] = fmaf(a[0], w[dx + 0], acc[dx][0]);
                acc[dx][1] = fmaf(a[1], w[dx + 1], acc[dx][1]);
                acc[dx][2] = fmaf(a[2], w[dx + 2], acc[dx][2]);
                acc[dx][3] = fmaf(a[3], w[dx + 3], acc[dx][3]);
            }
        }
        __syncthreads();   // protect smem before next chunk's fill
    }

    // ---- single final store (overwrites harness poison) ----
    const float scale = 1.0f / (float)C_;
    #pragma unroll
    for (int dx = 0; dx < ND; ++dx) {
        float4 v;
        v.x = acc[dx][0] * scale;
        v.y = acc[dx][1] * scale;
        v.z = acc[dx][2] * scale;
        v.w = acc[dx][3] * scale;
        *(float4*)&out[(((b * 81 + dy * ND + dx) * H_) + y0 + r) * W_ + x0 + q * 4] = v;
    }
}

extern "C" void kernel_launch(void* const* d_in, const int* in_sizes, int n_in,
                              void* d_out, int out_size)
{
    const float* in1 = (const float*)d_in[0];
    const float* in2 = (const float*)d_in[1];
    float* out = (float*)d_out;

    cudaFuncSetAttribute(corr_kernel,
                         cudaFuncAttributeMaxDynamicSharedMemorySize, SMEM_BYTES);

    dim3 grid(W_ / TX, H_ / TY, B_ * 3);  // (4, 12, 24) = 1152 blocks
    dim3 block(NTHR);
    corr_kernel<<<grid, block, SMEM_BYTES>>>(in1, in2, out);
}